// round 11
// baseline (speedup 1.0000x reference)
#include <cuda_runtime.h>
#include <cstdint>

// ---------------- problem constants (fixed by dataset) ----------------
#define NMAX 100000
#define EMAX 1250000
#define D    64
#define H    128
#define DV   (D / 4)   // 16 float4 per row

// ---------------- device scratch (static allocation, allowed) ---------
// Replay invariants: g_cnt + g_base zeroed by k_gather; g_stats/g_ticket
// reset by k_bn finalize; g_start/g_cur/g_srt/g_agg4 rewritten each replay.
__device__ int    g_cnt  [ NMAX ];    // in-degree counts
__device__ int    g_start[ NMAX ];    // CSR bin start per node
__device__ int    g_cur  [ NMAX ];    // fill cursor; after fill = bin end
__device__ int    g_srt  [ EMAX ];    // src ids grouped by dst
__device__ float4 g_agg4[ (size_t)NMAX * DV ];  // RAW mean-aggregate (no BN)
__device__ float  g_stats[ 2 * D ];   // colsum / colsumsq
__device__ float4 g_sc4[ DV ];        // BN scale per column (packed)
__device__ float4 g_sb4[ DV ];        // BN bias  per column (packed)
__device__ unsigned g_ticket;         // k_bn completion ticket
__device__ int    g_base;             // global bin allocator

// ---------------- helpers ---------------------------------------------
__device__ __forceinline__ float f2tf32f(float x) {
    uint32_t r;
    asm("cvt.rna.tf32.f32 %0, %1;" : "=r"(r) : "f"(x));
    return __uint_as_float(r);
}

__device__ __forceinline__ void mma_tf32(float* c, const uint32_t* a,
                                         uint32_t b0, uint32_t b1) {
    asm("mma.sync.aligned.m16n8k8.row.col.f32.tf32.tf32.f32 "
        "{%0,%1,%2,%3}, {%4,%5,%6,%7}, {%8,%9}, {%0,%1,%2,%3};"
        : "+f"(c[0]), "+f"(c[1]), "+f"(c[2]), "+f"(c[3])
        : "r"(a[0]), "r"(a[1]), "r"(a[2]), "r"(a[3]), "r"(b0), "r"(b1));
}

// ---------------- kernel A (parallel stream): BN stats + finalize -----
__global__ void k_bn(const float4* __restrict__ x4,
                     const float* __restrict__ gamma,
                     const float* __restrict__ beta, int N) {
    __shared__ float4 s_s4[16][16];
    __shared__ float4 s_q4[16][16];
    __shared__ bool   s_last;
    int t  = threadIdx.x;
    int c4 = t & 15, rg = t >> 4;
    float4 s = make_float4(0.f, 0.f, 0.f, 0.f);
    float4 q = make_float4(0.f, 0.f, 0.f, 0.f);
    for (int r = blockIdx.x * 16 + rg; r < N; r += gridDim.x * 16) {
        float4 v = x4[(size_t)r * DV + c4];
        s.x += v.x; s.y += v.y; s.z += v.z; s.w += v.w;
        q.x += v.x * v.x; q.y += v.y * v.y;
        q.z += v.z * v.z; q.w += v.w * v.w;
    }
    s_s4[rg][c4] = s; s_q4[rg][c4] = q;
    __syncthreads();
    #pragma unroll
    for (int off = 8; off >= 1; off >>= 1) {
        if (rg < off) {
            float4 a = s_s4[rg + off][c4];
            float4 b = s_q4[rg + off][c4];
            s_s4[rg][c4].x += a.x; s_s4[rg][c4].y += a.y;
            s_s4[rg][c4].z += a.z; s_s4[rg][c4].w += a.w;
            s_q4[rg][c4].x += b.x; s_q4[rg][c4].y += b.y;
            s_q4[rg][c4].z += b.z; s_q4[rg][c4].w += b.w;
        }
        __syncthreads();
    }
    if (t < 16) {
        float4 S = s_s4[0][t], Q = s_q4[0][t];
        atomicAdd(&g_stats[t * 4 + 0], S.x); atomicAdd(&g_stats[t * 4 + 1], S.y);
        atomicAdd(&g_stats[t * 4 + 2], S.z); atomicAdd(&g_stats[t * 4 + 3], S.w);
        atomicAdd(&g_stats[D + t * 4 + 0], Q.x); atomicAdd(&g_stats[D + t * 4 + 1], Q.y);
        atomicAdd(&g_stats[D + t * 4 + 2], Q.z); atomicAdd(&g_stats[D + t * 4 + 3], Q.w);
    }
    __threadfence();
    if (t == 0)
        s_last = (atomicAdd(&g_ticket, 1u) == (unsigned)gridDim.x - 1u);
    __syncthreads();
    if (s_last && t < D) {
        float invN = 1.0f / (float)N;
        float mean = g_stats[t] * invN;
        float var  = g_stats[D + t] * invN - mean * mean;
        float inv  = rsqrtf(var + 1e-5f);
        float g    = gamma[t];
        reinterpret_cast<float*>(g_sc4)[t] = inv * g;
        reinterpret_cast<float*>(g_sb4)[t] = beta[t] - mean * inv * g;
        g_stats[t] = 0.f; g_stats[D + t] = 0.f;   // reset for next replay
        if (t == 0) g_ticket = 0u;
        __threadfence();
    }
}

// ---------------- kernel 1: in-degree count ---------------------------
__global__ void k_count(const int* __restrict__ ei, int E, int N) {
    int i = blockIdx.x * blockDim.x + threadIdx.x;
    int stride = gridDim.x * blockDim.x;
    for (int e = i; e < E; e += stride) {
        int dst = ei[(size_t)E + e];
        if ((unsigned)dst < (unsigned)N) atomicAdd(&g_cnt[dst], 1);
    }
}

// ---------------- kernel 2: parallel bin offsets ----------------------
// Block-local inclusive scan + one atomicAdd per block to allocate its
// bin region (arrival order — gather only needs [start, end) per node).
__global__ void __launch_bounds__(1024)
k_offsets(int N) {
    __shared__ int s[1024];
    __shared__ int s_base;
    int t = threadIdx.x;
    int i = blockIdx.x * 1024 + t;
    int c = (i < N) ? g_cnt[i] : 0;
    s[t] = c;
    __syncthreads();
    for (int off = 1; off < 1024; off <<= 1) {
        int v = (t >= off) ? s[t - off] : 0;
        __syncthreads();
        s[t] += v;
        __syncthreads();
    }
    if (t == 1023) s_base = atomicAdd(&g_base, s[1023]);
    __syncthreads();
    if (i < N) {
        int st = s_base + s[t] - c;
        g_start[i] = st;
        g_cur[i]   = st;
    }
}

// ---------------- kernel 3: CSR fill (bin src ids by dst) -------------
__global__ void k_fill(const int* __restrict__ ei, int E, int N) {
    int i = blockIdx.x * blockDim.x + threadIdx.x;
    int stride = gridDim.x * blockDim.x;
    for (int e = i; e < E; e += stride) {
        int dst = ei[(size_t)E + e];
        int src = ei[e];
        if ((unsigned)dst >= (unsigned)N || (unsigned)src >= (unsigned)N) continue;
        int pos = atomicAdd(&g_cur[dst], 1);
        g_srt[pos] = src;
    }
}

// ---------------- kernel 4: high-occupancy CSR gather (raw mean) ------
// Warp per node, lane owns float2 of the 64-dim row. Register accumulate,
// writes RAW mean (BN affine deferred to fused). Zeroes g_cnt/g_base.
__global__ void __launch_bounds__(256)
k_gather(const float2* __restrict__ x2, int N) {
    int w    = threadIdx.x >> 5;
    int lane = threadIdx.x & 31;
    int node = blockIdx.x * 8 + w;
    if (threadIdx.x == 0 && blockIdx.x == 0) g_base = 0;   // replay invariant
    if (node >= N) return;
    if (lane == 0) g_cnt[node] = 0;                        // replay invariant
    int start = g_start[node];
    int end   = g_cur[node];
    float sx = 0.f, sy = 0.f;
    int e = start;
    for (; e + 4 <= end; e += 4) {
        int s0 = g_srt[e],     s1 = g_srt[e + 1];
        int s2 = g_srt[e + 2], s3 = g_srt[e + 3];
        float2 v0 = x2[(size_t)s0 * 32 + lane];
        float2 v1 = x2[(size_t)s1 * 32 + lane];
        float2 v2 = x2[(size_t)s2 * 32 + lane];
        float2 v3 = x2[(size_t)s3 * 32 + lane];
        sx += (v0.x + v1.x) + (v2.x + v3.x);
        sy += (v0.y + v1.y) + (v2.y + v3.y);
    }
    for (; e < end; e++) {
        int s0 = g_srt[e];
        float2 v0 = x2[(size_t)s0 * 32 + lane];
        sx += v0.x; sy += v0.y;
    }
    int cnt = end - start;
    float2 o = make_float2(0.f, 0.f);
    if (cnt > 0) {
        float inv = 1.0f / (float)cnt;
        o.x = sx * inv;
        o.y = sy * inv;
    }
    reinterpret_cast<float2*>(g_agg4)[(size_t)node * 32 + lane] = o;
}

// ---------------- kernel 5: tf32 tensor-core GEMM + classifier --------
// h = relu([sc*agg+sb (cnt>0), xn] @ [W_l; W_r] + b_l)
// out = relu(h @ W1 + b1) @ W2 + b2, straight from mma fragments.
#define U_STRIDE 36
#define W_STRIDE 132
__global__ void __launch_bounds__(256)
k_fused_tc(const float4* __restrict__ x4,
           const float* __restrict__ Wl, const float* __restrict__ bl,
           const float* __restrict__ Wr, const float* __restrict__ W1,
           const float* __restrict__ b1, const float* __restrict__ W2,
           const float* __restrict__ b2, float* __restrict__ out, int N) {
    __shared__ float s_u [128 * U_STRIDE];   // U chunk  [128 rows][32 k], tf32
    __shared__ float s_w [32 * W_STRIDE];    // W chunk  [32 k][128 h], tf32
    __shared__ float s_w1t[16 * 128];        // W1^T [j][h]
    __shared__ float s_bl[128];
    __shared__ float s_scf[64], s_sbf[64];

    int t    = threadIdx.x;
    int w    = t >> 5;
    int lane = t & 31;
    int g    = lane >> 2;     // group id 0..7
    int tq   = lane & 3;      // thread-in-quad 0..3
    int m0   = blockIdx.x * 128;

    if (t < 128) s_bl[t] = bl[t];
    if (t < 64)  s_scf[t] = reinterpret_cast<const float*>(g_sc4)[t];
    else if (t < 128) s_sbf[t - 64] = reinterpret_cast<const float*>(g_sb4)[t - 64];
    for (int i = t; i < 16 * 128; i += 256) {      // W1 [128][16] -> W1T[j][h]
        int c = i & 127, j = i >> 7;
        s_w1t[j * 128 + c] = W1[c * 16 + j];
    }

    float acc[16][4];
    #pragma unroll
    for (int n = 0; n < 16; n++)
        #pragma unroll
        for (int j = 0; j < 4; j++) acc[n][j] = 0.f;

    #pragma unroll
    for (int kb = 0; kb < 4; kb++) {
        __syncthreads();
        // ---- load U chunk: 128 rows x 32 k (tf32) ----
        #pragma unroll
        for (int ii = 0; ii < 4; ii++) {
            int i = t + 256 * ii;            // 0..1023 float4 units
            int row = i >> 3, k4 = i & 7;
            int node = m0 + row;
            int kg = kb * 32 + k4 * 4;
            float4 v = make_float4(0.f, 0.f, 0.f, 0.f);
            if (node < N) {
                if (kg < D) {
                    int cnt = g_cur[node] - g_start[node];
                    if (cnt > 0) {
                        v = g_agg4[(size_t)node * DV + (kg >> 2)];  // raw mean
                        int c = kg;
                        v.x = fmaf(v.x, s_scf[c + 0], s_sbf[c + 0]);
                        v.y = fmaf(v.y, s_scf[c + 1], s_sbf[c + 1]);
                        v.z = fmaf(v.z, s_scf[c + 2], s_sbf[c + 2]);
                        v.w = fmaf(v.w, s_scf[c + 3], s_sbf[c + 3]);
                    }
                } else {
                    int kx = (kg - D) >> 2;
                    v = x4[(size_t)node * DV + kx];
                    int c = kx * 4;
                    v.x = fmaf(v.x, s_scf[c + 0], s_sbf[c + 0]);
                    v.y = fmaf(v.y, s_scf[c + 1], s_sbf[c + 1]);
                    v.z = fmaf(v.z, s_scf[c + 2], s_sbf[c + 2]);
                    v.w = fmaf(v.w, s_scf[c + 3], s_sbf[c + 3]);
                }
            }
            float* p = &s_u[row * U_STRIDE + k4 * 4];
            p[0] = f2tf32f(v.x); p[1] = f2tf32f(v.y);
            p[2] = f2tf32f(v.z); p[3] = f2tf32f(v.w);
        }
        // ---- load W chunk: 32 k x 128 h (tf32) ----
        #pragma unroll
        for (int ii = 0; ii < 4; ii++) {
            int i = t + 256 * ii;            // 0..1023 float4 units
            int k = i >> 5, h4 = i & 31;
            int kg = kb * 32 + k;
            const float* src = (kg < D) ? (Wl + (size_t)kg * H + h4 * 4)
                                        : (Wr + (size_t)(kg - D) * H + h4 * 4);
            float4 v = *reinterpret_cast<const float4*>(src);
            float* p = &s_w[k * W_STRIDE + h4 * 4];
            p[0] = f2tf32f(v.x); p[1] = f2tf32f(v.y);
            p[2] = f2tf32f(v.z); p[3] = f2tf32f(v.w);
        }
        __syncthreads();

        // ---- A fragments for this chunk (4 k-steps of 8) ----
        uint32_t A[4][4];
        int arow = (w * 16 + g) * U_STRIDE;
        #pragma unroll
        for (int kk = 0; kk < 4; kk++) {
            int kof = kk * 8 + tq;
            A[kk][0] = __float_as_uint(s_u[arow + kof]);
            A[kk][1] = __float_as_uint(s_u[arow + 8 * U_STRIDE + kof]);
            A[kk][2] = __float_as_uint(s_u[arow + kof + 4]);
            A[kk][3] = __float_as_uint(s_u[arow + 8 * U_STRIDE + kof + 4]);
        }
        // ---- 16 n-tiles x 4 k-steps of mma ----
        #pragma unroll
        for (int nt = 0; nt < 16; nt++) {
            int bcol = nt * 8 + g;
            #pragma unroll
            for (int kk = 0; kk < 4; kk++) {
                uint32_t b0  = __float_as_uint(s_w[(kk * 8 + tq) * W_STRIDE + bcol]);
                uint32_t b1r = __float_as_uint(s_w[(kk * 8 + tq + 4) * W_STRIDE + bcol]);
                mma_tf32(acc[nt], A[kk], b0, b1r);
            }
        }
    }

    // ---- epilogue: bias + relu + classifier, straight from fragments ----
    float part[2][16];
    #pragma unroll
    for (int rr = 0; rr < 2; rr++)
        #pragma unroll
        for (int j = 0; j < 16; j++) part[rr][j] = 0.f;

    #pragma unroll
    for (int nt = 0; nt < 16; nt++) {
        int c0 = nt * 8 + 2 * tq;
        float h00 = fmaxf(acc[nt][0] + s_bl[c0],     0.f);
        float h01 = fmaxf(acc[nt][1] + s_bl[c0 + 1], 0.f);
        float h10 = fmaxf(acc[nt][2] + s_bl[c0],     0.f);
        float h11 = fmaxf(acc[nt][3] + s_bl[c0 + 1], 0.f);
        #pragma unroll
        for (int j = 0; j < 16; j++) {
            float w0 = s_w1t[j * 128 + c0];
            float w1 = s_w1t[j * 128 + c0 + 1];
            part[0][j] += h00 * w0 + h01 * w1;
            part[1][j] += h10 * w0 + h11 * w1;
        }
    }
    #pragma unroll
    for (int rr = 0; rr < 2; rr++)
        #pragma unroll
        for (int j = 0; j < 16; j++) {
            part[rr][j] += __shfl_xor_sync(0xffffffffu, part[rr][j], 1);
            part[rr][j] += __shfl_xor_sync(0xffffffffu, part[rr][j], 2);
        }

    if (tq == 0) {
        #pragma unroll
        for (int rr = 0; rr < 2; rr++) {
            int node = m0 + w * 16 + g + rr * 8;
            if (node < N) {
                float o0 = b2[0], o1 = b2[1];
                #pragma unroll
                for (int j = 0; j < 16; j++) {
                    float tv = fmaxf(part[rr][j] + b1[j], 0.f);
                    o0 += tv * W2[j * 2 + 0];
                    o1 += tv * W2[j * 2 + 1];
                }
                out[(size_t)node * 2 + 0] = o0;
                out[(size_t)node * 2 + 1] = o1;
            }
        }
    }
}

// ---------------- launcher (fork-join graph) ---------------------------
extern "C" void kernel_launch(void* const* d_in, const int* in_sizes, int n_in,
                              void* d_out, int out_size) {
    const float4* x4 = (const float4*)d_in[0];
    const float2* x2 = (const float2*)d_in[0];
    const int*    ei = (const int*)d_in[1];   // int64 ref -> int32 in harness
    int N = in_sizes[0] / D;
    int E = in_sizes[1] / 2;

    const int want[9] = {64, 64, 8192, 128, 8192, 2048, 16, 32, 2};
    const float* wptr[9] = {nullptr, nullptr, nullptr, nullptr, nullptr,
                            nullptr, nullptr, nullptr, nullptr};
    int j = 0;
    for (int i = 2; i < n_in && j < 9; i++) {
        if (in_sizes[i] == want[j]) { wptr[j] = (const float*)d_in[i]; j++; }
    }
    const float *gamma = wptr[0], *beta = wptr[1], *Wl = wptr[2], *bl = wptr[3],
                *Wr = wptr[4], *W1 = wptr[5], *b1 = wptr[6], *W2 = wptr[7],
                *b2 = wptr[8];
    float* out = (float*)d_out;

    // Lazy one-time stream/event creation: first call is the uncaptured
    // correctness run, so creation never happens during graph capture.
    static cudaStream_t s_bn = nullptr;
    static cudaEvent_t  ev_fork = nullptr, ev_join = nullptr;
    if (!s_bn) {
        cudaStreamCreateWithFlags(&s_bn, cudaStreamNonBlocking);
        cudaEventCreateWithFlags(&ev_fork, cudaEventDisableTiming);
        cudaEventCreateWithFlags(&ev_join, cudaEventDisableTiming);
    }

    // fork: BN stats on side stream, CSR chain on main stream
    cudaEventRecord(ev_fork, 0);
    cudaStreamWaitEvent(s_bn, ev_fork, 0);
    k_bn<<<592, 256, 0, s_bn>>>(x4, gamma, beta, N);
    cudaEventRecord(ev_join, s_bn);

    k_count<<<1024, 256>>>(ei, E, N);
    k_offsets<<<(N + 1023) / 1024, 1024>>>(N);
    k_fill<<<2048, 256>>>(ei, E, N);
    k_gather<<<(N + 7) / 8, 256>>>(x2, N);

    // join: fused GEMM needs both branches
    cudaStreamWaitEvent(0, ev_join, 0);
    k_fused_tc<<<(N + 127) / 128, 256>>>(x4, Wl, bl, Wr, W1, b1, W2, b2, out, N);
}